// round 17
// baseline (speedup 1.0000x reference)
#include <cuda_runtime.h>
#include <math.h>

// Shapes (fixed by the problem)
#define BB  2
#define NN  512
#define HID 128
#define DD  32    // Chebyshev orders; measured: truncation below fp32 noise at 32

#define PRO_BLOCKS DD                 // 32 prologue blocks (1 node each)
#define MAIN_BLOCKS ((BB * NN) / 4)   // 256 main blocks (4 rows each)
#define TOTAL_BLOCKS (PRO_BLOCKS + MAIN_BLOCKS)   // 288 <= 296 co-resident @2/SM

// Scratch (static device globals; no allocation)
__device__ float g_inv_hd;           // 2 / dmax
__device__ float g_G[DD * HID];      // network(+Wo) at Chebyshev nodes
__device__ float g_C[DD * HID];      // Chebyshev coefficients
__device__ unsigned g_flag_dmax;     // 1 when g_inv_hd ready
__device__ unsigned g_arrive;        // prologue-internal 32-block barrier
__device__ unsigned g_done;          // prologue blocks finished (g_C ready at 32)
__device__ unsigned g_fin;           // main blocks finished; last resets all

// NOTE: float4-accessed members MUST sit at 16B-aligned offsets inside the
// union (the R16 crash): part @0, sG @8192, buf @24576 — all 16B-aligned.
union SmemU {
    struct {
        float part[16][HID];                // per-k-group partials (8KB)   @0
        float sG[DD][HID];                  // staged G (16KB)              @8192
        float buf[HID];                     // activations (1 node)         @24576
        float costab[DD];
        float red[16];
        float sdmax;
    } pro;
    struct {
        float sx[NN * 2];                   // @0 (float4 accessed)
        float sred[16][DD];
        float sredc[4][DD];
    } mn;
};

__global__ __launch_bounds__(512, 2) void fused_kernel(
    const float* __restrict__ x,
    const float* __restrict__ W10, const float* __restrict__ b10,
    const float* __restrict__ W20, const float* __restrict__ b20,
    const float* __restrict__ W11, const float* __restrict__ b11,
    const float* __restrict__ W21, const float* __restrict__ b21,
    const float* __restrict__ W12, const float* __restrict__ b12,
    const float* __restrict__ W22, const float* __restrict__ b22,
    const float* __restrict__ Wo,  const float* __restrict__ bo,
    float* __restrict__ out)
{
    __shared__ __align__(16) SmemU sm;
    const int tid = threadIdx.x;

    if (blockIdx.x < PRO_BLOCKS) {
        // ============== PROLOGUE PATH (R15 fast design, 1 node/block) ==============
        const int kq   = tid >> 5;             // 0..15: owns k = kq*8 .. kq*8+7
        const int c4   = tid & 31;             // owns columns 4*c4 .. 4*c4+3
        const int lane = tid & 31;
        const int wrp  = tid >> 5;

        const float* Ws[6] = {W20, W11, W21, W12, W22, Wo};
        const float* bs[6] = {b20, b11, b21, b12, b22, (const float*)0};

        // dmax = 2*max||x||: one float4 per thread (exactly 2048 floats),
        // warp shfl-max + tiny tree; max is order-invariant -> deterministic.
        {
            float4 v = reinterpret_cast<const float4*>(x)[tid];
            float m = fmaxf(fmaf(v.x, v.x, v.y * v.y), fmaf(v.z, v.z, v.w * v.w));
            #pragma unroll
            for (int off = 16; off > 0; off >>= 1)
                m = fmaxf(m, __shfl_xor_sync(0xffffffffu, m, off));
            if (lane == 0) sm.pro.red[wrp] = m;
            __syncthreads();
            if (tid == 0) {
                float mm = sm.pro.red[0];
                #pragma unroll
                for (int g = 1; g < 16; g++) mm = fmaxf(mm, sm.pro.red[g]);
                float dm = 2.0f * sqrtf(mm) * 1.000001f + 1e-6f;
                sm.pro.sdmax = dm;
                if (blockIdx.x == 0) {
                    g_inv_hd = 2.0f / dm;
                    __threadfence();
                    atomicExch(&g_flag_dmax, 1u);    // release to main blocks
                }
            }
            __syncthreads();
        }
        const float dmax = sm.pro.sdmax;

        // layer 0 (scalar input): node = blockIdx.x
        if (tid < HID) {
            float d = 0.5f * (cospif((blockIdx.x + 0.5f) * (1.0f / DD)) + 1.0f) * dmax;
            float a = fmaf(d, W10[tid], b10[tid]);
            sm.pro.buf[tid] = a / (1.0f + expf(-a));
        }
        __syncthreads();

        #pragma unroll
        for (int l = 0; l < 6; l++) {
            // weights L2-resident during replays: 8 LDG.128, MLP 8
            float4 wv[8];
            #pragma unroll
            for (int kk = 0; kk < 8; kk++)
                wv[kk] = *reinterpret_cast<const float4*>(
                    &Ws[l][(kq * 8 + kk) * HID + 4 * c4]);
            float h0 = 0.0f, h1 = 0.0f, h2 = 0.0f, h3 = 0.0f;
            #pragma unroll
            for (int kk = 0; kk < 8; kk++) {
                const float a = sm.pro.buf[kq * 8 + kk];   // warp broadcast
                h0 = fmaf(a, wv[kk].x, h0);
                h1 = fmaf(a, wv[kk].y, h1);
                h2 = fmaf(a, wv[kk].z, h2);
                h3 = fmaf(a, wv[kk].w, h3);
            }
            reinterpret_cast<float4*>(sm.pro.part[kq])[c4] = make_float4(h0, h1, h2, h3);
            __syncthreads();
            // finalize column (threads 0..127), deterministic sequential combine
            if (tid < HID) {
                float v = bs[l] ? bs[l][tid] : 0.0f;
                #pragma unroll
                for (int g = 0; g < 16; g++) v += sm.pro.part[g][tid];
                if (l == 1 || l == 3) v = v / (1.0f + expf(-v));   // silu
                if (l < 5) sm.pro.buf[tid] = v;
                else g_G[blockIdx.x * HID + tid] = v;
            }
            __syncthreads();
        }

        // barrier across the 32 prologue blocks (G complete)
        __threadfence();
        if (tid == 0) {
            atomicAdd(&g_arrive, 1u);
            while (*(volatile unsigned*)&g_arrive < (unsigned)PRO_BLOCKS) __nanosleep(32);
        }
        __syncthreads();
        __threadfence();

        // DCT-II: block produces coefficient row k = blockIdx.x
        if (tid < DD) {
            int num = (blockIdx.x * (2 * tid + 1)) & (4 * DD - 1);   // cospi period 2
            sm.pro.costab[tid] = cospif((float)num * (1.0f / (2.0f * DD)));
        }
        for (int t = tid; t < DD * HID / 4; t += 512)
            reinterpret_cast<float4*>(sm.pro.sG)[t] =
                __ldcg(reinterpret_cast<const float4*>(g_G) + t);
        __syncthreads();

        {
            const int mq = tid >> 7, c = tid & (HID - 1);
            float acc = 0.0f;
            #pragma unroll
            for (int mm = 0; mm < 8; mm++) {
                const int m = mq * 8 + mm;
                acc = fmaf(sm.pro.costab[m], sm.pro.sG[m][c], acc);
            }
            sm.pro.part[mq][c] = acc;
        }
        __syncthreads();
        if (tid < HID) {
            float wgt = (blockIdx.x == 0) ? (1.0f / DD) : (2.0f / DD);
            float acc = (sm.pro.part[0][tid] + sm.pro.part[1][tid])
                      + (sm.pro.part[2][tid] + sm.pro.part[3][tid]);
            g_C[blockIdx.x * HID + tid] = acc * wgt;
        }
        __threadfence();
        __syncthreads();
        if (tid == 0) atomicAdd(&g_done, 1u);    // release coefficients
        return;
    }

    // ===================== MAIN PATH (runs concurrently) =====================
    const int mb = blockIdx.x - PRO_BLOCKS;      // 0..255
    const int b  = mb >> 7;                      // 128 blocks per batch

    // stage x via float4 (overlaps the dmax wait)
    for (int t = tid; t < NN * 2 / 4; t += 512)
        reinterpret_cast<float4*>(sm.mn.sx)[t] =
            reinterpret_cast<const float4*>(x + b * NN * 2)[t];

    if (tid == 0) {
        while (*(volatile unsigned*)&g_flag_dmax == 0u) __nanosleep(32);
    }
    __syncthreads();         // orders sx stores AND the flag acquire
    __threadfence();
    const float inv_hd = *(volatile float*)&g_inv_hd;

    const int w    = tid >> 5;                   // warp 0..15
    const int lane = tid & 31;
    const int r    = w >> 2;                     // row-in-block 0..3
    const int h    = w & 3;                      // j-quarter 0..3
    const int i    = ((mb & 127) << 2) + r;      // row within batch
    const float xi0 = sm.mn.sx[2 * i], xi1 = sm.mn.sx[2 * i + 1];

    float s[DD];
    {
        const int j0 = h * 128;
        const int ja = j0 + lane, jb = ja + 32, jc = ja + 64, jd = ja + 96;
        float dxa = xi0 - sm.mn.sx[2 * ja], dya = xi1 - sm.mn.sx[2 * ja + 1];
        float dxb = xi0 - sm.mn.sx[2 * jb], dyb = xi1 - sm.mn.sx[2 * jb + 1];
        float dxc = xi0 - sm.mn.sx[2 * jc], dyc = xi1 - sm.mn.sx[2 * jc + 1];
        float dxd = xi0 - sm.mn.sx[2 * jd], dyd = xi1 - sm.mn.sx[2 * jd + 1];
        float za = fmaf(sqrtf(fmaf(dxa, dxa, dya * dya)), inv_hd, -1.0f);
        float zb = fmaf(sqrtf(fmaf(dxb, dxb, dyb * dyb)), inv_hd, -1.0f);
        float zc = fmaf(sqrtf(fmaf(dxc, dxc, dyc * dyc)), inv_hd, -1.0f);
        float zd = fmaf(sqrtf(fmaf(dxd, dxd, dyd * dyd)), inv_hd, -1.0f);
        za = fminf(fmaxf(za, -1.0f), 1.0f);
        zb = fminf(fmaxf(zb, -1.0f), 1.0f);
        zc = fminf(fmaxf(zc, -1.0f), 1.0f);
        zd = fminf(fmaxf(zd, -1.0f), 1.0f);

        s[0] = 4.0f;                             // T_0 == 1, 4 j's per lane
        s[1] = (za + zb) + (zc + zd);
        float t0a = 1.0f, t1a = za, z2a = za + za;
        float t0b = 1.0f, t1b = zb, z2b = zb + zb;
        float t0c = 1.0f, t1c = zc, z2c = zc + zc;
        float t0d = 1.0f, t1d = zd, z2d = zd + zd;
        #pragma unroll
        for (int k = 2; k < DD; k++) {
            float ta = fmaf(z2a, t1a, -t0a); t0a = t1a; t1a = ta;
            float tb = fmaf(z2b, t1b, -t0b); t0b = t1b; t1b = tb;
            float tc = fmaf(z2c, t1c, -t0c); t0c = t1c; t1c = tc;
            float td = fmaf(z2d, t1d, -t0d); t0d = t1d; t1d = td;
            s[k] = (ta + tb) + (tc + td);
        }
    }

    // reduce-scatter butterfly: lane ends holding k = lane
    #pragma unroll
    for (int st = 0; st < 5; st++) {
        const int off = 16 >> st;
        const int len = 16 >> st;
        const bool hi = (lane & off) != 0;
        #pragma unroll
        for (int k = 0; k < len; k++) {
            float send = hi ? s[k] : s[k + len];
            float recv = __shfl_xor_sync(0xffffffffu, send, off);
            s[k] = (hi ? s[k + len] : s[k]) + recv;
        }
    }
    sm.mn.sred[w][lane] = s[0];
    __syncthreads();

    // combine the 4 j-quarters per row (before the coefficient wait)
    if (tid < 4 * DD) {
        const int rr = tid >> 5, kk = tid & 31;
        sm.mn.sredc[rr][kk] = ((sm.mn.sred[4 * rr][kk]     + sm.mn.sred[4 * rr + 1][kk])
                             + (sm.mn.sred[4 * rr + 2][kk] + sm.mn.sred[4 * rr + 3][kk]))
                              * (1.0f / (float)NN);
    }

    // wait for coefficients (prologue ran concurrently, likely done)
    if (tid == 0) {
        while (*(volatile unsigned*)&g_done < (unsigned)PRO_BLOCKS) __nanosleep(32);
    }
    __syncthreads();         // orders sredc stores AND the g_done acquire
    __threadfence();

    // contract with C: warp owns 32 columns, lane owns 1 (coalesced, L1-bypass)
    const int c0 = h * 32 + lane;
    float acc = bo[c0];
    #pragma unroll
    for (int k = 0; k < DD; k++)
        acc = fmaf(sm.mn.sredc[r][k], __ldcg(&g_C[k * HID + c0]), acc);
    const int gi = b * NN + i;
    out[gi * HID + c0] = acc;

    // replay-safe reset: last main block restores all counters to 0
    __threadfence();
    __syncthreads();
    if (tid == 0) {
        unsigned old = atomicAdd(&g_fin, 1u);
        if (old == (unsigned)(MAIN_BLOCKS - 1)) {
            g_flag_dmax = 0u;
            g_arrive    = 0u;
            g_done      = 0u;
            g_fin       = 0u;
            __threadfence();
        }
    }
}

// ---------------------------------------------------------------------------
// Launch: ONE graph-capturable kernel; prologue (32 blocks, ~2-3 us critical
// path) overlaps the main accumulation (256 blocks); single co-resident wave;
// all counters restored to 0 before exit (bitwise replay-safe).
// Input order: x, W1_0,b1_0,W2_0,b2_0, W1_1,b1_1,W2_1,b2_1, W1_2,b1_2,W2_2,b2_2, Wo,bo
// ---------------------------------------------------------------------------
extern "C" void kernel_launch(void* const* d_in, const int* in_sizes, int n_in,
                              void* d_out, int out_size)
{
    const float* x   = (const float*)d_in[0];
    const float* W10 = (const float*)d_in[1];
    const float* b10 = (const float*)d_in[2];
    const float* W20 = (const float*)d_in[3];
    const float* b20 = (const float*)d_in[4];
    const float* W11 = (const float*)d_in[5];
    const float* b11 = (const float*)d_in[6];
    const float* W21 = (const float*)d_in[7];
    const float* b21 = (const float*)d_in[8];
    const float* W12 = (const float*)d_in[9];
    const float* b12 = (const float*)d_in[10];
    const float* W22 = (const float*)d_in[11];
    const float* b22 = (const float*)d_in[12];
    const float* Wo  = (const float*)d_in[13];
    const float* bo  = (const float*)d_in[14];
    float* out = (float*)d_out;

    fused_kernel<<<TOTAL_BLOCKS, 512>>>(x, W10, b10, W20, b20, W11, b11,
                                        W21, b21, W12, b12, W22, b22, Wo, bo, out);
}